// round 8
// baseline (speedup 1.0000x reference)
#include <cuda_runtime.h>

// Problem constants (fixed shapes from reference setup_inputs)
#define B 64
#define N 10000
#define D 128
#define F 4
#define CHUNKS 111            // 64*111 = 7104 CTAs = exactly 8 waves of 888 (148 SM x 6 CTA)
#define LN_EPS 0.001f
#define ROW_V (D / 4)         // 32 float4 per row

// Deterministic partial-sum scratch: [B][CHUNKS][32] float4
__device__ float4 g_partials4[B * CHUNKS * ROW_V];
// Pre-computed gathered-part GEMV result: [B][128]
__device__ float g_ypre[B * D];
// Completion counters per batch (zero-init; self-resetting per launch)
__device__ int g_count[B];

// Release-acquire fetch-add: orders prior global stores (release) and makes
// peers' stores visible (acquire) without gpu-scope MEMBAR/CCTL.IVALL.
__device__ __forceinline__ int atom_add_acqrel(int* p, int v) {
    int old;
    asm volatile("atom.add.acq_rel.gpu.s32 %0, [%1], %2;"
                 : "=r"(old) : "l"(p), "r"(v) : "memory");
    return old;
}

// ---------------------------------------------------------------------------
// grid (CHUNKS, B) x 256 threads, 6 CTAs/SM.
// Phase 1 (all):      streaming float4 sum of ~90 H rows -> g_partials4
// Phase 1b (chunk 0): y_pre[b] = bias + relu(gather(H)) @ W[0:512]  (overlapped)
// Phase 2 (last CTA per batch): mean + mean @ W[512:640] + y_pre, relu, LN.
// ---------------------------------------------------------------------------
__global__ __launch_bounds__(256, 6) void fused_kernel(
    const float* __restrict__ H,
    const int*   __restrict__ indice,
    const float* __restrict__ W,      // [640, 128] row-major
    const float* __restrict__ bias,   // [128]
    const float* __restrict__ gamma,  // [128]
    const float* __restrict__ beta,   // [128]
    float*       __restrict__ out)    // [B, 1, 128]
{
    const int chunk = blockIdx.x;
    const int b     = blockIdx.y;
    const int tid   = threadIdx.x;
    const int lane  = tid & 31;
    const int grp   = tid >> 5;   // 8 row groups

    __shared__ float4 sm[256];            // phase-1 reduce; reused as part[] later
    __shared__ float4 emb4[(F * D) / 4];  // 512 gathered floats (chunk-0 only)
    __shared__ float  meanrow[D];
    __shared__ int    sidx[F];
    __shared__ float  red_mu[4], red_var[4];
    __shared__ int    is_last;
    float* emb  = (float*)emb4;
    float* part = (float*)sm;

    // ================= Phase 1: streaming partial sum (balanced ranges) ========
    const int r0 = (chunk * N) / CHUNKS;
    const int r1 = ((chunk + 1) * N) / CHUNKS;

    const float4* __restrict__ p =
        (const float4*)H + ((long long)b * N + r0 + grp) * ROW_V + lane;

    float4 a0 = make_float4(0.f,0.f,0.f,0.f);
    float4 a1 = make_float4(0.f,0.f,0.f,0.f);

    int cnt = r1 - (r0 + grp);            // rows this thread covers, stride 8
    while (cnt >= 32) {                   // 4 independent loads in flight
        float4 v0 = __ldcs(p);
        float4 v1 = __ldcs(p +  8 * ROW_V);
        float4 v2 = __ldcs(p + 16 * ROW_V);
        float4 v3 = __ldcs(p + 24 * ROW_V);
        a0.x += v0.x; a0.y += v0.y; a0.z += v0.z; a0.w += v0.w;
        a1.x += v1.x; a1.y += v1.y; a1.z += v1.z; a1.w += v1.w;
        a0.x += v2.x; a0.y += v2.y; a0.z += v2.z; a0.w += v2.w;
        a1.x += v3.x; a1.y += v3.y; a1.z += v3.z; a1.w += v3.w;
        p += 32 * ROW_V;
        cnt -= 32;
    }
    while (cnt > 0) {
        float4 v0 = __ldcs(p);
        a0.x += v0.x; a0.y += v0.y; a0.z += v0.z; a0.w += v0.w;
        p += 8 * ROW_V;
        cnt -= 8;
    }
    a0.x += a1.x; a0.y += a1.y; a0.z += a1.z; a0.w += a1.w;

    sm[tid] = a0;
    __syncthreads();

    if (tid < 32) {
        float4 s = sm[lane];
        #pragma unroll
        for (int g = 1; g < 8; g++) {
            float4 v = sm[g * 32 + lane];
            s.x += v.x; s.y += v.y; s.z += v.z; s.w += v.w;
        }
        g_partials4[(b * CHUNKS + chunk) * ROW_V + lane] = s;
    }
    __syncthreads();

    // ========== Phase 1b (chunk 0 only): pre-GEMV of gathered 512 dims =========
    if (chunk == 0) {
        if (tid < F) sidx[tid] = __ldg(&indice[b * F + tid]);
        __syncthreads();
        {   // gather 4 rows (relu): 2 rows per pass
            const int f0 = tid >> 7;
            const int d  = tid & 127;
            #pragma unroll
            for (int q = 0; q < 2; q++) {
                const int f = f0 + 2 * q;
                emb[f * D + d] = fmaxf(__ldg(&H[((long long)b * N + sidx[f]) * D + d]), 0.0f);
            }
        }
        __syncthreads();
        {   // GEMV rows 0..511: group g -> rows [64g, 64g+64), float4 col-group c4
            const int c4 = tid & 31;
            const int g  = tid >> 5;
            const int rb = g * 64;
            const float4* __restrict__ W4 = (const float4*)W;  // [640][32]

            float4 acc0 = make_float4(0.f,0.f,0.f,0.f);
            float4 acc1 = make_float4(0.f,0.f,0.f,0.f);
            #pragma unroll 8
            for (int j = 0; j < 64; j += 2) {
                float  e0 = emb[rb + j];
                float  e1 = emb[rb + j + 1];
                float4 w0 = __ldg(&W4[(rb + j    ) * ROW_V + c4]);
                float4 w1 = __ldg(&W4[(rb + j + 1) * ROW_V + c4]);
                acc0.x = fmaf(e0, w0.x, acc0.x); acc0.y = fmaf(e0, w0.y, acc0.y);
                acc0.z = fmaf(e0, w0.z, acc0.z); acc0.w = fmaf(e0, w0.w, acc0.w);
                acc1.x = fmaf(e1, w1.x, acc1.x); acc1.y = fmaf(e1, w1.y, acc1.y);
                acc1.z = fmaf(e1, w1.z, acc1.z); acc1.w = fmaf(e1, w1.w, acc1.w);
            }
            acc0.x += acc1.x; acc0.y += acc1.y; acc0.z += acc1.z; acc0.w += acc1.w;
            sm[g * ROW_V + c4] = acc0;
        }
        __syncthreads();
        if (tid < D) {   // combine 8 groups + bias -> y_pre
            float y = __ldg(&bias[tid]);
            #pragma unroll
            for (int g = 0; g < 8; g++) y += part[g * D + tid];
            g_ypre[b * D + tid] = y;
        }
        __syncthreads();
    }

    // ================= last-CTA election =================
    if (tid == 0) {
        int old = atom_add_acqrel(&g_count[b], 1);
        is_last = (old == CHUNKS - 1);
        if (is_last) g_count[b] = 0;  // self-reset for next graph replay
    }
    __syncthreads();
    if (!is_last) return;

    // ================= Phase 2: short tail for batch b =================
    // mean row (threads 0..127), partials via L2, 4 independent accumulators
    if (tid < D) {
        const float* gp = (const float*)g_partials4 + (long long)b * CHUNKS * D + tid;
        float s0 = 0.f, s1 = 0.f, s2 = 0.f, s3 = 0.f;
        int c = 0;
        for (; c + 3 < CHUNKS; c += 4) {
            s0 += __ldcg(gp + (c    ) * D);
            s1 += __ldcg(gp + (c + 1) * D);
            s2 += __ldcg(gp + (c + 2) * D);
            s3 += __ldcg(gp + (c + 3) * D);
        }
        for (; c < CHUNKS; c++) s0 += __ldcg(gp + c * D);
        meanrow[tid] = ((s0 + s1) + (s2 + s3)) * (1.0f / (float)N);
    }
    __syncthreads();

    // GEMV rows 512..639: group g -> 16 rows, float4 col-group c4
    {
        const int c4 = tid & 31;
        const int g  = tid >> 5;
        const int rb = g * 16;
        const float4* __restrict__ W4 = (const float4*)W + (long long)(F * D) * ROW_V;

        float4 acc0 = make_float4(0.f,0.f,0.f,0.f);
        float4 acc1 = make_float4(0.f,0.f,0.f,0.f);
        #pragma unroll
        for (int j = 0; j < 16; j += 2) {
            float  e0 = meanrow[rb + j];
            float  e1 = meanrow[rb + j + 1];
            float4 w0 = __ldg(&W4[(rb + j    ) * ROW_V + c4]);
            float4 w1 = __ldg(&W4[(rb + j + 1) * ROW_V + c4]);
            acc0.x = fmaf(e0, w0.x, acc0.x); acc0.y = fmaf(e0, w0.y, acc0.y);
            acc0.z = fmaf(e0, w0.z, acc0.z); acc0.w = fmaf(e0, w0.w, acc0.w);
            acc1.x = fmaf(e1, w1.x, acc1.x); acc1.y = fmaf(e1, w1.y, acc1.y);
            acc1.z = fmaf(e1, w1.z, acc1.z); acc1.w = fmaf(e1, w1.w, acc1.w);
        }
        acc0.x += acc1.x; acc0.y += acc1.y; acc0.z += acc1.z; acc0.w += acc1.w;
        __syncthreads();
        sm[g * ROW_V + c4] = acc0;
    }
    __syncthreads();

    // combine + y_pre, relu, layernorm (threads 0..127)
    float x = 0.f;
    if (tid < D) {
        x = __ldcg(&g_ypre[b * D + tid]);
        #pragma unroll
        for (int g = 0; g < 8; g++) x += part[g * D + tid];
        x = fmaxf(x, 0.0f);

        float v = x;
        #pragma unroll
        for (int o = 16; o > 0; o >>= 1) v += __shfl_xor_sync(0xffffffffu, v, o);
        if (lane == 0) red_mu[tid >> 5] = v;
    }
    __syncthreads();
    if (tid < D) {
        float mu = (red_mu[0] + red_mu[1] + red_mu[2] + red_mu[3]) * (1.0f / (float)D);
        float dx = x - mu;
        float v2 = dx * dx;
        #pragma unroll
        for (int o = 16; o > 0; o >>= 1) v2 += __shfl_xor_sync(0xffffffffu, v2, o);
        if (lane == 0) red_var[tid >> 5] = v2;
    }
    __syncthreads();
    if (tid < D) {
        float mu  = (red_mu[0]  + red_mu[1]  + red_mu[2]  + red_mu[3])  * (1.0f / (float)D);
        float var = (red_var[0] + red_var[1] + red_var[2] + red_var[3]) * (1.0f / (float)D);
        out[b * D + tid] = (x - mu) * rsqrtf(var + LN_EPS) * __ldg(&gamma[tid]) + __ldg(&beta[tid]);
    }
}

// ---------------------------------------------------------------------------
extern "C" void kernel_launch(void* const* d_in, const int* in_sizes, int n_in,
                              void* d_out, int out_size) {
    const float* H      = (const float*)d_in[0];
    const int*   indice = (const int*)  d_in[1];
    const float* W      = (const float*)d_in[2];
    const float* bias   = (const float*)d_in[3];
    const float* gamma  = (const float*)d_in[4];
    const float* beta   = (const float*)d_in[5];
    float* out = (float*)d_out;

    dim3 grid(CHUNKS, B);
    fused_kernel<<<grid, 256>>>(H, indice, W, bias, gamma, beta, out);
}

// round 9
// speedup vs baseline: 1.1412x; 1.1412x over previous
#include <cuda_runtime.h>

// Problem constants (fixed shapes from reference setup_inputs)
#define B 64
#define N 10000
#define D 128
#define F 4
#define CHUNKS 37             // 64*37 = 2368 CTAs = exactly 2 waves of 1184 (148 SM x 8 CTA)
#define LN_EPS 0.001f
#define ROW_V (D / 4)         // 32 float4 per row

// Deterministic partial-sum scratch: [B][CHUNKS][32] float4
__device__ float4 g_partials4[B * CHUNKS * ROW_V];
// Pre-computed gathered-part GEMV result: [B][128]
__device__ float g_ypre[B * D];
// Completion counters per batch (zero-init; self-resetting per launch)
__device__ int g_count[B];

// Release-acquire fetch-add: orders prior global stores (release) and makes
// peers' stores visible (acquire) without gpu-scope MEMBAR/CCTL.IVALL.
__device__ __forceinline__ int atom_add_acqrel(int* p, int v) {
    int old;
    asm volatile("atom.add.acq_rel.gpu.s32 %0, [%1], %2;"
                 : "=r"(old) : "l"(p), "r"(v) : "memory");
    return old;
}

// ---------------------------------------------------------------------------
// grid (CHUNKS, B) x 256 threads, 8 CTAs/SM (<=32 regs).
// Phase 1 (all):      streaming float4 sum of ~270 H rows -> g_partials4
// Phase 1b (chunk 0): y_pre[b] = bias + relu(gather(H)) @ W[0:512]  (overlapped)
// Phase 2 (last CTA per batch): mean + mean @ W[512:640] + y_pre, relu, LN.
// ---------------------------------------------------------------------------
__global__ __launch_bounds__(256, 8) void fused_kernel(
    const float* __restrict__ H,
    const int*   __restrict__ indice,
    const float* __restrict__ W,      // [640, 128] row-major
    const float* __restrict__ bias,   // [128]
    const float* __restrict__ gamma,  // [128]
    const float* __restrict__ beta,   // [128]
    float*       __restrict__ out)    // [B, 1, 128]
{
    const int chunk = blockIdx.x;
    const int b     = blockIdx.y;
    const int tid   = threadIdx.x;
    const int lane  = tid & 31;
    const int grp   = tid >> 5;   // 8 row groups

    __shared__ float4 sm[256];            // phase-1 reduce; reused as part[] later
    __shared__ float4 emb4[(F * D) / 4];  // 512 gathered floats (chunk-0 only)
    __shared__ float  meanrow[D];
    __shared__ int    sidx[F];
    __shared__ float  red_mu[4], red_var[4];
    __shared__ int    is_last;
    float* emb  = (float*)emb4;
    float* part = (float*)sm;

    // ================= Phase 1: streaming partial sum (balanced ranges) ========
    const int r0 = (chunk * N) / CHUNKS;
    const int r1 = ((chunk + 1) * N) / CHUNKS;

    // 32-bit element indexing: 64*10000*32 float4 = 20.48M < 2^31
    const float4* __restrict__ p =
        (const float4*)H + (b * N + r0 + grp) * ROW_V + lane;

    float4 a0 = make_float4(0.f,0.f,0.f,0.f);
    float4 a1 = make_float4(0.f,0.f,0.f,0.f);

    int cnt = r1 - (r0 + grp);            // rows this thread covers, stride 8
    while (cnt >= 32) {                   // 4 independent loads in flight
        float4 v0 = __ldcs(p);
        float4 v1 = __ldcs(p +  8 * ROW_V);
        float4 v2 = __ldcs(p + 16 * ROW_V);
        float4 v3 = __ldcs(p + 24 * ROW_V);
        a0.x += v0.x; a0.y += v0.y; a0.z += v0.z; a0.w += v0.w;
        a1.x += v1.x; a1.y += v1.y; a1.z += v1.z; a1.w += v1.w;
        a0.x += v2.x; a0.y += v2.y; a0.z += v2.z; a0.w += v2.w;
        a1.x += v3.x; a1.y += v3.y; a1.z += v3.z; a1.w += v3.w;
        p += 32 * ROW_V;
        cnt -= 32;
    }
    while (cnt > 0) {
        float4 v0 = __ldcs(p);
        a0.x += v0.x; a0.y += v0.y; a0.z += v0.z; a0.w += v0.w;
        p += 8 * ROW_V;
        cnt -= 8;
    }
    a0.x += a1.x; a0.y += a1.y; a0.z += a1.z; a0.w += a1.w;

    sm[tid] = a0;
    __syncthreads();

    if (tid < 32) {
        float4 s = sm[lane];
        #pragma unroll
        for (int g = 1; g < 8; g++) {
            float4 v = sm[g * 32 + lane];
            s.x += v.x; s.y += v.y; s.z += v.z; s.w += v.w;
        }
        g_partials4[(b * CHUNKS + chunk) * ROW_V + lane] = s;
    }
    __syncthreads();

    // ========== Phase 1b (chunk 0 only): pre-GEMV of gathered 512 dims =========
    if (chunk == 0) {
        if (tid < F) sidx[tid] = __ldg(&indice[b * F + tid]);
        __syncthreads();
        {   // gather 4 rows (relu): 2 rows per pass
            const int f0 = tid >> 7;
            const int d  = tid & 127;
            #pragma unroll
            for (int q = 0; q < 2; q++) {
                const int f = f0 + 2 * q;
                emb[f * D + d] = fmaxf(__ldg(&H[(b * N + sidx[f]) * D + d]), 0.0f);
            }
        }
        __syncthreads();
        {   // GEMV rows 0..511: group g -> rows [64g, 64g+64), float4 col-group c4
            const int c4 = tid & 31;
            const int g  = tid >> 5;
            const int rb = g * 64;
            const float4* __restrict__ W4 = (const float4*)W;  // [640][32]

            float4 acc0 = make_float4(0.f,0.f,0.f,0.f);
            float4 acc1 = make_float4(0.f,0.f,0.f,0.f);
            #pragma unroll 8
            for (int j = 0; j < 64; j += 2) {
                float  e0 = emb[rb + j];
                float  e1 = emb[rb + j + 1];
                float4 w0 = __ldg(&W4[(rb + j    ) * ROW_V + c4]);
                float4 w1 = __ldg(&W4[(rb + j + 1) * ROW_V + c4]);
                acc0.x = fmaf(e0, w0.x, acc0.x); acc0.y = fmaf(e0, w0.y, acc0.y);
                acc0.z = fmaf(e0, w0.z, acc0.z); acc0.w = fmaf(e0, w0.w, acc0.w);
                acc1.x = fmaf(e1, w1.x, acc1.x); acc1.y = fmaf(e1, w1.y, acc1.y);
                acc1.z = fmaf(e1, w1.z, acc1.z); acc1.w = fmaf(e1, w1.w, acc1.w);
            }
            acc0.x += acc1.x; acc0.y += acc1.y; acc0.z += acc1.z; acc0.w += acc1.w;
            __syncthreads();          // sm[] free (phase-1 reduce done)
            sm[g * ROW_V + c4] = acc0;
        }
        __syncthreads();
        if (tid < D) {   // combine 8 groups + bias -> y_pre
            float y = __ldg(&bias[tid]);
            #pragma unroll
            for (int g = 0; g < 8; g++) y += part[g * D + tid];
            g_ypre[b * D + tid] = y;
        }
        __syncthreads();
    }

    // ================= last-CTA election =================
    if (tid == 0) {
        int old = atom_add_acqrel(&g_count[b], 1);
        is_last = (old == CHUNKS - 1);
        if (is_last) g_count[b] = 0;  // self-reset for next graph replay
    }
    __syncthreads();
    if (!is_last) return;

    // ================= Phase 2: short tail for batch b =================
    // mean row (threads 0..127), partials via L2, 4 independent accumulators
    if (tid < D) {
        const float* gp = (const float*)g_partials4 + b * CHUNKS * D + tid;
        float s0 = 0.f, s1 = 0.f, s2 = 0.f, s3 = 0.f;
        int c = 0;
        for (; c + 3 < CHUNKS; c += 4) {
            s0 += __ldcg(gp + (c    ) * D);
            s1 += __ldcg(gp + (c + 1) * D);
            s2 += __ldcg(gp + (c + 2) * D);
            s3 += __ldcg(gp + (c + 3) * D);
        }
        for (; c < CHUNKS; c++) s0 += __ldcg(gp + c * D);
        meanrow[tid] = ((s0 + s1) + (s2 + s3)) * (1.0f / (float)N);
    }
    __syncthreads();

    // GEMV rows 512..639: group g -> 16 rows, float4 col-group c4
    {
        const int c4 = tid & 31;
        const int g  = tid >> 5;
        const int rb = g * 16;
        const float4* __restrict__ W4 = (const float4*)W + (F * D) * ROW_V;

        float4 acc0 = make_float4(0.f,0.f,0.f,0.f);
        float4 acc1 = make_float4(0.f,0.f,0.f,0.f);
        #pragma unroll
        for (int j = 0; j < 16; j += 2) {
            float  e0 = meanrow[rb + j];
            float  e1 = meanrow[rb + j + 1];
            float4 w0 = __ldg(&W4[(rb + j    ) * ROW_V + c4]);
            float4 w1 = __ldg(&W4[(rb + j + 1) * ROW_V + c4]);
            acc0.x = fmaf(e0, w0.x, acc0.x); acc0.y = fmaf(e0, w0.y, acc0.y);
            acc0.z = fmaf(e0, w0.z, acc0.z); acc0.w = fmaf(e0, w0.w, acc0.w);
            acc1.x = fmaf(e1, w1.x, acc1.x); acc1.y = fmaf(e1, w1.y, acc1.y);
            acc1.z = fmaf(e1, w1.z, acc1.z); acc1.w = fmaf(e1, w1.w, acc1.w);
        }
        acc0.x += acc1.x; acc0.y += acc1.y; acc0.z += acc1.z; acc0.w += acc1.w;
        __syncthreads();
        sm[g * ROW_V + c4] = acc0;
    }
    __syncthreads();

    // combine + y_pre, relu, layernorm (threads 0..127)
    float x = 0.f;
    if (tid < D) {
        x = __ldcg(&g_ypre[b * D + tid]);
        #pragma unroll
        for (int g = 0; g < 8; g++) x += part[g * D + tid];
        x = fmaxf(x, 0.0f);

        float v = x;
        #pragma unroll
        for (int o = 16; o > 0; o >>= 1) v += __shfl_xor_sync(0xffffffffu, v, o);
        if (lane == 0) red_mu[tid >> 5] = v;
    }
    __syncthreads();
    if (tid < D) {
        float mu = (red_mu[0] + red_mu[1] + red_mu[2] + red_mu[3]) * (1.0f / (float)D);
        float dx = x - mu;
        float v2 = dx * dx;
        #pragma unroll
        for (int o = 16; o > 0; o >>= 1) v2 += __shfl_xor_sync(0xffffffffu, v2, o);
        if (lane == 0) red_var[tid >> 5] = v2;
    }
    __syncthreads();
    if (tid < D) {
        float mu  = (red_mu[0]  + red_mu[1]  + red_mu[2]  + red_mu[3])  * (1.0f / (float)D);
        float var = (red_var[0] + red_var[1] + red_var[2] + red_var[3]) * (1.0f / (float)D);
        out[b * D + tid] = (x - mu) * rsqrtf(var + LN_EPS) * __ldg(&gamma[tid]) + __ldg(&beta[tid]);
    }
}

// ---------------------------------------------------------------------------
extern "C" void kernel_launch(void* const* d_in, const int* in_sizes, int n_in,
                              void* d_out, int out_size) {
    const float* H      = (const float*)d_in[0];
    const int*   indice = (const int*)  d_in[1];
    const float* W      = (const float*)d_in[2];
    const float* bias   = (const float*)d_in[3];
    const float* gamma  = (const float*)d_in[4];
    const float* beta   = (const float*)d_in[5];
    float* out = (float*)d_out;

    dim3 grid(CHUNKS, B);
    fused_kernel<<<grid, 256>>>(H, indice, W, bias, gamma, beta, out);
}

// round 10
// speedup vs baseline: 1.1683x; 1.0237x over previous
#include <cuda_runtime.h>

// Problem constants (fixed shapes from reference setup_inputs)
#define B 64
#define N 10000
#define D 128
#define F 4
#define CHUNKS 37
#define ROWS_PER_CHUNK ((N + CHUNKS - 1) / CHUNKS)   // 271
#define LN_EPS 0.001f
#define ROW_V (D / 4)                                // 32 float4 per row

// Deterministic partial-sum scratch: [B][CHUNKS][32] float4
__device__ float4 g_partials4[B * CHUNKS * ROW_V];
// Pre-computed gathered-part GEMV result: [B][128]
__device__ float g_ypre[B * D];

// ---------------------------------------------------------------------------
// Kernel 1: grid (CHUNKS+1, B) x 256 threads.
//   chunk <  CHUNKS : streaming float4 sum of H rows (exact R3 structure)
//   chunk == CHUNKS : y_pre[b] = bias + relu(gather(H,idx)) @ W[0:512]
// ---------------------------------------------------------------------------
__global__ __launch_bounds__(256) void stream_kernel(
    const float* __restrict__ H,
    const int*   __restrict__ indice,
    const float* __restrict__ W,      // [640, 128] row-major
    const float* __restrict__ bias)   // [128]
{
    const int chunk = blockIdx.x;
    const int b     = blockIdx.y;
    const int tid   = threadIdx.x;
    const int lane  = tid & 31;
    const int grp   = tid >> 5;   // 8 row groups

    __shared__ float4 sm[256];

    if (chunk < CHUNKS) {
        // ============ streaming partial sum (R3-proven body) ============
        const int r0 = chunk * ROWS_PER_CHUNK;
        int r1 = r0 + ROWS_PER_CHUNK;
        if (r1 > N) r1 = N;

        const float4* __restrict__ Hv = (const float4*)H;

        float4 a0 = make_float4(0.f,0.f,0.f,0.f);
        float4 a1 = make_float4(0.f,0.f,0.f,0.f);
        float4 a2 = make_float4(0.f,0.f,0.f,0.f);
        float4 a3 = make_float4(0.f,0.f,0.f,0.f);

        int r = r0 + grp;
        for (; r + 24 < r1; r += 32) {
            float4 v0 = __ldcs(&Hv[(b * N + r     ) * ROW_V + lane]);
            float4 v1 = __ldcs(&Hv[(b * N + r +  8) * ROW_V + lane]);
            float4 v2 = __ldcs(&Hv[(b * N + r + 16) * ROW_V + lane]);
            float4 v3 = __ldcs(&Hv[(b * N + r + 24) * ROW_V + lane]);
            a0.x += v0.x; a0.y += v0.y; a0.z += v0.z; a0.w += v0.w;
            a1.x += v1.x; a1.y += v1.y; a1.z += v1.z; a1.w += v1.w;
            a2.x += v2.x; a2.y += v2.y; a2.z += v2.z; a2.w += v2.w;
            a3.x += v3.x; a3.y += v3.y; a3.z += v3.z; a3.w += v3.w;
        }
        for (; r < r1; r += 8) {
            float4 v0 = __ldcs(&Hv[(b * N + r) * ROW_V + lane]);
            a0.x += v0.x; a0.y += v0.y; a0.z += v0.z; a0.w += v0.w;
        }
        a0.x += a1.x + a2.x + a3.x;
        a0.y += a1.y + a2.y + a3.y;
        a0.z += a1.z + a2.z + a3.z;
        a0.w += a1.w + a2.w + a3.w;

        sm[tid] = a0;
        __syncthreads();

        if (tid < 32) {
            float4 s = sm[lane];
            #pragma unroll
            for (int g = 1; g < 8; g++) {
                float4 v = sm[g * 32 + lane];
                s.x += v.x; s.y += v.y; s.z += v.z; s.w += v.w;
            }
            g_partials4[(b * CHUNKS + chunk) * ROW_V + lane] = s;
        }
    } else {
        // ============ y_pre: gather + GEMV rows 0..511 (overlapped) ============
        __shared__ float4 emb4[(F * D) / 4];   // 512 floats
        __shared__ int    sidx[F];
        float* emb  = (float*)emb4;
        float* part = (float*)sm;

        if (tid < F) sidx[tid] = __ldg(&indice[b * F + tid]);
        __syncthreads();
        {   // gather 4 rows (relu): 2 rows per pass of 256 threads
            const int f0 = tid >> 7;
            const int d  = tid & 127;
            #pragma unroll
            for (int q = 0; q < 2; q++) {
                const int f = f0 + 2 * q;
                emb[f * D + d] = fmaxf(__ldg(&H[(b * N + sidx[f]) * D + d]), 0.0f);
            }
        }
        __syncthreads();
        {   // GEMV rows 0..511: group g (tid>>5) -> 64 rows, float4 col-group c4
            const int c4 = tid & 31;
            const int g  = tid >> 5;
            const int rb = g * 64;
            const float4* __restrict__ W4 = (const float4*)W;  // [640][32]

            float4 acc0 = make_float4(0.f,0.f,0.f,0.f);
            float4 acc1 = make_float4(0.f,0.f,0.f,0.f);
            #pragma unroll 8
            for (int j = 0; j < 64; j += 2) {
                float  e0 = emb[rb + j];
                float  e1 = emb[rb + j + 1];
                float4 w0 = __ldg(&W4[(rb + j    ) * ROW_V + c4]);
                float4 w1 = __ldg(&W4[(rb + j + 1) * ROW_V + c4]);
                acc0.x = fmaf(e0, w0.x, acc0.x); acc0.y = fmaf(e0, w0.y, acc0.y);
                acc0.z = fmaf(e0, w0.z, acc0.z); acc0.w = fmaf(e0, w0.w, acc0.w);
                acc1.x = fmaf(e1, w1.x, acc1.x); acc1.y = fmaf(e1, w1.y, acc1.y);
                acc1.z = fmaf(e1, w1.z, acc1.z); acc1.w = fmaf(e1, w1.w, acc1.w);
            }
            acc0.x += acc1.x; acc0.y += acc1.y; acc0.z += acc1.z; acc0.w += acc1.w;
            sm[g * ROW_V + c4] = acc0;
        }
        __syncthreads();
        if (tid < D) {   // combine 8 groups + bias -> y_pre
            float y = __ldg(&bias[tid]);
            #pragma unroll
            for (int g = 0; g < 8; g++) y += part[g * D + tid];
            g_ypre[b * D + tid] = y;
        }
    }
}

// ---------------------------------------------------------------------------
// Kernel 2: grid B x 256 threads. mean reduce + mean @ W[512:640] + y_pre,
// relu, layernorm. All operands L2-hot (partials 19KB/CTA, W tail 64KB).
// ---------------------------------------------------------------------------
__global__ __launch_bounds__(256) void final_kernel(
    const float* __restrict__ W,      // [640, 128]
    const float* __restrict__ gamma,  // [128]
    const float* __restrict__ beta,   // [128]
    float*       __restrict__ out)    // [B, 1, 128]
{
    const int b    = blockIdx.x;
    const int tid  = threadIdx.x;
    const int lane = tid & 31;
    const int d    = tid & 127;
    const int half = tid >> 7;        // 0: even chunks, 1: odd chunks

    __shared__ float meanhalf[2][D];
    __shared__ float meanrow[D];
    __shared__ float4 part4[8 * ROW_V];
    __shared__ float red_mu[4], red_var[4];
    float* part = (float*)part4;

    // ---- mean reduce: 2 threads per d, even/odd chunk interleave ----
    {
        const float* gp = (const float*)g_partials4 + b * CHUNKS * D + d;
        float s = 0.f;
        for (int c = half; c < CHUNKS; c += 2)
            s += gp[c * D];
        meanhalf[half][d] = s;
    }
    __syncthreads();
    if (tid < D)
        meanrow[tid] = (meanhalf[0][tid] + meanhalf[1][tid]) * (1.0f / (float)N);
    __syncthreads();

    // ---- GEMV rows 512..639: warp w -> 16 rows, float4 col-group c4 ----
    {
        const int c4 = tid & 31;
        const int w  = tid >> 5;
        const int rb = w * 16;
        const float4* __restrict__ W4 = (const float4*)W + (F * D) * ROW_V;

        float4 acc0 = make_float4(0.f,0.f,0.f,0.f);
        float4 acc1 = make_float4(0.f,0.f,0.f,0.f);
        #pragma unroll
        for (int j = 0; j < 16; j += 2) {
            float  e0 = meanrow[rb + j];
            float  e1 = meanrow[rb + j + 1];
            float4 w0 = __ldg(&W4[(rb + j    ) * ROW_V + c4]);
            float4 w1 = __ldg(&W4[(rb + j + 1) * ROW_V + c4]);
            acc0.x = fmaf(e0, w0.x, acc0.x); acc0.y = fmaf(e0, w0.y, acc0.y);
            acc0.z = fmaf(e0, w0.z, acc0.z); acc0.w = fmaf(e0, w0.w, acc0.w);
            acc1.x = fmaf(e1, w1.x, acc1.x); acc1.y = fmaf(e1, w1.y, acc1.y);
            acc1.z = fmaf(e1, w1.z, acc1.z); acc1.w = fmaf(e1, w1.w, acc1.w);
        }
        acc0.x += acc1.x; acc0.y += acc1.y; acc0.z += acc1.z; acc0.w += acc1.w;
        part4[w * ROW_V + c4] = acc0;
    }
    __syncthreads();

    // ---- combine + y_pre, relu, layernorm (threads 0..127) ----
    float x = 0.f;
    if (tid < D) {
        x = g_ypre[b * D + tid];
        #pragma unroll
        for (int g = 0; g < 8; g++) x += part[g * D + tid];
        x = fmaxf(x, 0.0f);

        float v = x;
        #pragma unroll
        for (int o = 16; o > 0; o >>= 1) v += __shfl_xor_sync(0xffffffffu, v, o);
        if (lane == 0) red_mu[tid >> 5] = v;
    }
    __syncthreads();
    if (tid < D) {
        float mu = (red_mu[0] + red_mu[1] + red_mu[2] + red_mu[3]) * (1.0f / (float)D);
        float dx = x - mu;
        float v2 = dx * dx;
        #pragma unroll
        for (int o = 16; o > 0; o >>= 1) v2 += __shfl_xor_sync(0xffffffffu, v2, o);
        if (lane == 0) red_var[tid >> 5] = v2;
    }
    __syncthreads();
    if (tid < D) {
        float mu  = (red_mu[0]  + red_mu[1]  + red_mu[2]  + red_mu[3])  * (1.0f / (float)D);
        float var = (red_var[0] + red_var[1] + red_var[2] + red_var[3]) * (1.0f / (float)D);
        out[b * D + tid] = (x - mu) * rsqrtf(var + LN_EPS) * __ldg(&gamma[tid]) + __ldg(&beta[tid]);
    }
}

// ---------------------------------------------------------------------------
extern "C" void kernel_launch(void* const* d_in, const int* in_sizes, int n_in,
                              void* d_out, int out_size) {
    const float* H      = (const float*)d_in[0];
    const int*   indice = (const int*)  d_in[1];
    const float* W      = (const float*)d_in[2];
    const float* bias   = (const float*)d_in[3];
    const float* gamma  = (const float*)d_in[4];
    const float* beta   = (const float*)d_in[5];
    float* out = (float*)d_out;

    dim3 grid1(CHUNKS + 1, B);
    stream_kernel<<<grid1, 256>>>(H, indice, W, bias);
    final_kernel<<<B, 256>>>(W, gamma, beta, out);
}

// round 11
// speedup vs baseline: 1.2199x; 1.0442x over previous
#include <cuda_runtime.h>

// Problem constants (fixed shapes from reference setup_inputs)
#define B 64
#define N 10000
#define D 128
#define F 4
#define CHUNKS 37
#define ROWS_PER_CHUNK ((N + CHUNKS - 1) / CHUNKS)   // 271
#define LN_EPS 0.001f
#define ROW_V (D / 4)                                // 32 float4 per row

// Deterministic partial-sum scratch: [B][CHUNKS][32] float4
__device__ float4 g_partials4[B * CHUNKS * ROW_V];
// Pre-computed gathered-part GEMV result: [B][128]
__device__ float g_ypre[B * D];

// ---------------------------------------------------------------------------
// Kernel 1: grid (CHUNKS+1, B) x 256 threads.
//   chunk <  CHUNKS : streaming float4 sum of H rows
//   chunk == CHUNKS : y_pre[b] = bias + relu(gather(H,idx)) @ W[0:512]
// Each CTA triggers programmatic launch completion right after its stores.
// ---------------------------------------------------------------------------
__global__ __launch_bounds__(256) void stream_kernel(
    const float* __restrict__ H,
    const int*   __restrict__ indice,
    const float* __restrict__ W,      // [640, 128] row-major
    const float* __restrict__ bias)   // [128]
{
    const int chunk = blockIdx.x;
    const int b     = blockIdx.y;
    const int tid   = threadIdx.x;
    const int lane  = tid & 31;
    const int grp   = tid >> 5;   // 8 row groups

    __shared__ float4 sm[256];

    if (chunk < CHUNKS) {
        // ============ streaming partial sum ============
        const int r0 = chunk * ROWS_PER_CHUNK;
        int r1 = r0 + ROWS_PER_CHUNK;
        if (r1 > N) r1 = N;

        const float4* __restrict__ Hv = (const float4*)H;

        float4 a0 = make_float4(0.f,0.f,0.f,0.f);
        float4 a1 = make_float4(0.f,0.f,0.f,0.f);
        float4 a2 = make_float4(0.f,0.f,0.f,0.f);
        float4 a3 = make_float4(0.f,0.f,0.f,0.f);

        int r = r0 + grp;
        for (; r + 24 < r1; r += 32) {
            float4 v0 = __ldcs(&Hv[(b * N + r     ) * ROW_V + lane]);
            float4 v1 = __ldcs(&Hv[(b * N + r +  8) * ROW_V + lane]);
            float4 v2 = __ldcs(&Hv[(b * N + r + 16) * ROW_V + lane]);
            float4 v3 = __ldcs(&Hv[(b * N + r + 24) * ROW_V + lane]);
            a0.x += v0.x; a0.y += v0.y; a0.z += v0.z; a0.w += v0.w;
            a1.x += v1.x; a1.y += v1.y; a1.z += v1.z; a1.w += v1.w;
            a2.x += v2.x; a2.y += v2.y; a2.z += v2.z; a2.w += v2.w;
            a3.x += v3.x; a3.y += v3.y; a3.z += v3.z; a3.w += v3.w;
        }
        for (; r < r1; r += 8) {
            float4 v0 = __ldcs(&Hv[(b * N + r) * ROW_V + lane]);
            a0.x += v0.x; a0.y += v0.y; a0.z += v0.z; a0.w += v0.w;
        }
        a0.x += a1.x + a2.x + a3.x;
        a0.y += a1.y + a2.y + a3.y;
        a0.z += a1.z + a2.z + a3.z;
        a0.w += a1.w + a2.w + a3.w;

        sm[tid] = a0;
        __syncthreads();

        if (tid < 32) {
            float4 s = sm[lane];
            #pragma unroll
            for (int g = 1; g < 8; g++) {
                float4 v = sm[g * 32 + lane];
                s.x += v.x; s.y += v.y; s.z += v.z; s.w += v.w;
            }
            g_partials4[(b * CHUNKS + chunk) * ROW_V + lane] = s;
        }
        __syncthreads();
        cudaTriggerProgrammaticLaunchCompletion();
    } else {
        // ============ y_pre: gather + GEMV rows 0..511 (overlapped) ============
        __shared__ float4 emb4[(F * D) / 4];   // 512 floats
        __shared__ int    sidx[F];
        float* emb  = (float*)emb4;
        float* part = (float*)sm;

        if (tid < F) sidx[tid] = __ldg(&indice[b * F + tid]);
        __syncthreads();
        {   // gather 4 rows (relu): 2 rows per pass of 256 threads
            const int f0 = tid >> 7;
            const int d  = tid & 127;
            #pragma unroll
            for (int q = 0; q < 2; q++) {
                const int f = f0 + 2 * q;
                emb[f * D + d] = fmaxf(__ldg(&H[(b * N + sidx[f]) * D + d]), 0.0f);
            }
        }
        __syncthreads();
        {   // GEMV rows 0..511: group g (tid>>5) -> 64 rows, float4 col-group c4
            const int c4 = tid & 31;
            const int g  = tid >> 5;
            const int rb = g * 64;
            const float4* __restrict__ W4 = (const float4*)W;  // [640][32]

            float4 acc0 = make_float4(0.f,0.f,0.f,0.f);
            float4 acc1 = make_float4(0.f,0.f,0.f,0.f);
            #pragma unroll 8
            for (int j = 0; j < 64; j += 2) {
                float  e0 = emb[rb + j];
                float  e1 = emb[rb + j + 1];
                float4 w0 = __ldg(&W4[(rb + j    ) * ROW_V + c4]);
                float4 w1 = __ldg(&W4[(rb + j + 1) * ROW_V + c4]);
                acc0.x = fmaf(e0, w0.x, acc0.x); acc0.y = fmaf(e0, w0.y, acc0.y);
                acc0.z = fmaf(e0, w0.z, acc0.z); acc0.w = fmaf(e0, w0.w, acc0.w);
                acc1.x = fmaf(e1, w1.x, acc1.x); acc1.y = fmaf(e1, w1.y, acc1.y);
                acc1.z = fmaf(e1, w1.z, acc1.z); acc1.w = fmaf(e1, w1.w, acc1.w);
            }
            acc0.x += acc1.x; acc0.y += acc1.y; acc0.z += acc1.z; acc0.w += acc1.w;
            sm[g * ROW_V + c4] = acc0;
        }
        __syncthreads();
        if (tid < D) {   // combine 8 groups + bias -> y_pre
            float y = __ldg(&bias[tid]);
            #pragma unroll
            for (int g = 0; g < 8; g++) y += part[g * D + tid];
            g_ypre[b * D + tid] = y;
        }
        __syncthreads();
        cudaTriggerProgrammaticLaunchCompletion();
    }
}

// ---------------------------------------------------------------------------
// Kernel 2 (PDL consumer): grid B x 256 threads.
// Prefetches all stream-independent operands (W tail, gamma, beta) into
// registers BEFORE cudaGridDependencySynchronize, so only the true dependent
// chain (partials -> mean -> GEMV -> LN) is exposed after the wait.
// ---------------------------------------------------------------------------
__global__ __launch_bounds__(256) void final_kernel(
    const float* __restrict__ W,      // [640, 128]
    const float* __restrict__ gamma,  // [128]
    const float* __restrict__ beta,   // [128]
    float*       __restrict__ out)    // [B, 1, 128]
{
    const int b    = blockIdx.x;
    const int tid  = threadIdx.x;
    const int lane = tid & 31;
    const int d    = tid & 127;
    const int half = tid >> 7;        // 0: even chunks, 1: odd chunks

    __shared__ float meanhalf[2][D];
    __shared__ float meanrow[D];
    __shared__ float4 part4[8 * ROW_V];
    __shared__ float red_mu[4], red_var[4];
    float* part = (float*)part4;

    // ---- prefetch W tail rows [512+rb, 512+rb+16) x col-group c4 ----
    const int c4 = tid & 31;
    const int w  = tid >> 5;
    const int rb = w * 16;
    const float4* __restrict__ W4 = (const float4*)W + (F * D) * ROW_V;

    float4 wreg[16];
    #pragma unroll
    for (int j = 0; j < 16; j++)
        wreg[j] = __ldg(&W4[(rb + j) * ROW_V + c4]);

    float gam = 0.f, bet = 0.f;
    if (tid < D) {
        gam = __ldg(&gamma[tid]);
        bet = __ldg(&beta[tid]);
    }

    // ---- wait for producer grid's memory to be visible ----
    cudaGridDependencySynchronize();

    // ---- mean reduce: 2 threads per d, even/odd chunk interleave, 4 accs ----
    {
        const float* gp = (const float*)g_partials4 + b * CHUNKS * D + d;
        float s0 = 0.f, s1 = 0.f, s2 = 0.f, s3 = 0.f;
        int c = half;
        for (; c + 6 < CHUNKS; c += 8) {
            s0 += __ldcg(gp + (c    ) * D);
            s1 += __ldcg(gp + (c + 2) * D);
            s2 += __ldcg(gp + (c + 4) * D);
            s3 += __ldcg(gp + (c + 6) * D);
        }
        for (; c < CHUNKS; c += 2) s0 += __ldcg(gp + c * D);
        meanhalf[half][d] = (s0 + s1) + (s2 + s3);
    }
    __syncthreads();
    if (tid < D)
        meanrow[tid] = (meanhalf[0][tid] + meanhalf[1][tid]) * (1.0f / (float)N);
    __syncthreads();

    // ---- GEMV rows 512..639 with prefetched W ----
    {
        float4 acc0 = make_float4(0.f,0.f,0.f,0.f);
        float4 acc1 = make_float4(0.f,0.f,0.f,0.f);
        #pragma unroll
        for (int j = 0; j < 16; j += 2) {
            float e0 = meanrow[rb + j];
            float e1 = meanrow[rb + j + 1];
            acc0.x = fmaf(e0, wreg[j].x, acc0.x); acc0.y = fmaf(e0, wreg[j].y, acc0.y);
            acc0.z = fmaf(e0, wreg[j].z, acc0.z); acc0.w = fmaf(e0, wreg[j].w, acc0.w);
            acc1.x = fmaf(e1, wreg[j+1].x, acc1.x); acc1.y = fmaf(e1, wreg[j+1].y, acc1.y);
            acc1.z = fmaf(e1, wreg[j+1].z, acc1.z); acc1.w = fmaf(e1, wreg[j+1].w, acc1.w);
        }
        acc0.x += acc1.x; acc0.y += acc1.y; acc0.z += acc1.z; acc0.w += acc1.w;
        part4[w * ROW_V + c4] = acc0;
    }
    __syncthreads();

    // ---- combine + y_pre, relu, layernorm (threads 0..127) ----
    float x = 0.f;
    if (tid < D) {
        x = __ldcg(&g_ypre[b * D + tid]);
        #pragma unroll
        for (int g = 0; g < 8; g++) x += part[g * D + tid];
        x = fmaxf(x, 0.0f);

        float v = x;
        #pragma unroll
        for (int o = 16; o > 0; o >>= 1) v += __shfl_xor_sync(0xffffffffu, v, o);
        if (lane == 0) red_mu[tid >> 5] = v;
    }
    __syncthreads();
    if (tid < D) {
        float mu = (red_mu[0] + red_mu[1] + red_mu[2] + red_mu[3]) * (1.0f / (float)D);
        float dx = x - mu;
        float v2 = dx * dx;
        #pragma unroll
        for (int o = 16; o > 0; o >>= 1) v2 += __shfl_xor_sync(0xffffffffu, v2, o);
        if (lane == 0) red_var[tid >> 5] = v2;
    }
    __syncthreads();
    if (tid < D) {
        float mu  = (red_mu[0]  + red_mu[1]  + red_mu[2]  + red_mu[3])  * (1.0f / (float)D);
        float var = (red_var[0] + red_var[1] + red_var[2] + red_var[3]) * (1.0f / (float)D);
        out[b * D + tid] = (x - mu) * rsqrtf(var + LN_EPS) * gam + bet;
    }
}

// ---------------------------------------------------------------------------
extern "C" void kernel_launch(void* const* d_in, const int* in_sizes, int n_in,
                              void* d_out, int out_size) {
    const float* H      = (const float*)d_in[0];
    const int*   indice = (const int*)  d_in[1];
    const float* W      = (const float*)d_in[2];
    const float* bias   = (const float*)d_in[3];
    const float* gamma  = (const float*)d_in[4];
    const float* beta   = (const float*)d_in[5];
    float* out = (float*)d_out;

    dim3 grid1(CHUNKS + 1, B);
    stream_kernel<<<grid1, 256>>>(H, indice, W, bias);

    // PDL: final_kernel launches while stream_kernel drains; its prologue
    // (W prefetch etc.) overlaps, and it blocks at cudaGridDependencySynchronize.
    cudaLaunchConfig_t cfg = {};
    cfg.gridDim  = dim3(B, 1, 1);
    cfg.blockDim = dim3(256, 1, 1);
    cfg.dynamicSmemBytes = 0;
    cfg.stream = 0;
    cudaLaunchAttribute attrs[1];
    attrs[0].id = cudaLaunchAttributeProgrammaticStreamSerialization;
    attrs[0].val.programmaticStreamSerializationAllowed = 1;
    cfg.attrs = attrs;
    cfg.numAttrs = 1;
    cudaLaunchKernelEx(&cfg, final_kernel, W, gamma, beta, out);
}